// round 1
// baseline (speedup 1.0000x reference)
#include <cuda_runtime.h>
#include <math.h>

#define BSZ      64
#define DFEAT    196608            // 3*256*256
#define KCHUNK   128               // gram partial blocks per matrix
#define CHUNK    (DFEAT / KCHUNK)  // 1536
#define TK       128
#define NTILE    (CHUNK / TK)      // 12
#define JSBLK    768
#define ADVN     16384
#define OUTER    30
#define INNER    200
#define L2E      1.4426950408889634f
#define EPS_GW   0.0005f
#define KSCALE   (L2E / EPS_GW)    // base-2 scaling of -cost/eps
#define LOGP2    (-6.0f)           // log2(1/64)

// ---- device scratch (no allocations allowed; fully rewritten each launch) ----
__device__ float g_part[2 * KCHUNK * 4096];  // gram partials, 4 MB
__device__ float g_lse[2 * DFEAT];           // per-position LSE for sr/hr
__device__ float g_js[2 * JSBLK];            // per-block KL partial sums
__device__ float g_adv;                      // sum softplus(-disc)
__device__ float g_gw;                       // GW distance

// ============================================================
// Kernel 1: Gram partials  G = X X^T  (64x64), K-chunked
// ============================================================
__global__ void gram_kernel(const float* __restrict__ lr,
                            const float* __restrict__ sr) {
    __shared__ float tile[64][TK + 1];  // pitch 129 floats
    const float* X = blockIdx.y ? sr : lr;
    float* out = g_part + (blockIdx.y * KCHUNK + blockIdx.x) * 4096;

    int tid = threadIdx.x;          // 256 threads
    int ty = tid >> 4, tx = tid & 15;
    float acc[4][4];
#pragma unroll
    for (int r = 0; r < 4; ++r)
#pragma unroll
        for (int c = 0; c < 4; ++c) acc[r][c] = 0.f;

    long k0base = (long)blockIdx.x * CHUNK;
    for (int t = 0; t < NTILE; ++t) {
        long k0 = k0base + (long)t * TK;
        for (int idx = tid; idx < 64 * TK; idx += 256) {
            int r = idx >> 7, c = idx & (TK - 1);
            tile[r][c] = X[(long)r * DFEAT + k0 + c];
        }
        __syncthreads();
#pragma unroll 4
        for (int k = 0; k < TK; ++k) {
            float a0 = tile[4 * ty + 0][k];
            float a1 = tile[4 * ty + 1][k];
            float a2 = tile[4 * ty + 2][k];
            float a3 = tile[4 * ty + 3][k];
            float b0 = tile[4 * tx + 0][k];
            float b1 = tile[4 * tx + 1][k];
            float b2 = tile[4 * tx + 2][k];
            float b3 = tile[4 * tx + 3][k];
            acc[0][0] = fmaf(a0, b0, acc[0][0]);
            acc[0][1] = fmaf(a0, b1, acc[0][1]);
            acc[0][2] = fmaf(a0, b2, acc[0][2]);
            acc[0][3] = fmaf(a0, b3, acc[0][3]);
            acc[1][0] = fmaf(a1, b0, acc[1][0]);
            acc[1][1] = fmaf(a1, b1, acc[1][1]);
            acc[1][2] = fmaf(a1, b2, acc[1][2]);
            acc[1][3] = fmaf(a1, b3, acc[1][3]);
            acc[2][0] = fmaf(a2, b0, acc[2][0]);
            acc[2][1] = fmaf(a2, b1, acc[2][1]);
            acc[2][2] = fmaf(a2, b2, acc[2][2]);
            acc[2][3] = fmaf(a2, b3, acc[2][3]);
            acc[3][0] = fmaf(a3, b0, acc[3][0]);
            acc[3][1] = fmaf(a3, b1, acc[3][1]);
            acc[3][2] = fmaf(a3, b2, acc[3][2]);
            acc[3][3] = fmaf(a3, b3, acc[3][3]);
        }
        __syncthreads();
    }
#pragma unroll
    for (int r = 0; r < 4; ++r)
#pragma unroll
        for (int c = 0; c < 4; ++c)
            out[(4 * ty + r) * 64 + 4 * tx + c] = acc[r][c];
}

// ============================================================
// Kernel 2: per-position online logsumexp over batch (sr, hr)
// ============================================================
__global__ void js_lse_kernel(const float* __restrict__ sr,
                              const float* __restrict__ hr) {
    int pos = blockIdx.x * blockDim.x + threadIdx.x;  // 768*256 = 196608
    const float* ps = sr + pos;
    const float* ph = hr + pos;
    float m1 = -1e30f, s1 = 0.f, m2 = -1e30f, s2 = 0.f;
#pragma unroll 4
    for (int b = 0; b < BSZ; ++b) {
        float v = ps[(long)b * DFEAT];
        float nm = fmaxf(m1, v);
        s1 = s1 * exp2f((m1 - nm) * L2E) + exp2f((v - nm) * L2E);
        m1 = nm;
        float w = ph[(long)b * DFEAT];
        float nw = fmaxf(m2, w);
        s2 = s2 * exp2f((m2 - nw) * L2E) + exp2f((w - nw) * L2E);
        m2 = nw;
    }
    g_lse[pos]         = m1 + __logf(s1);
    g_lse[DFEAT + pos] = m2 + __logf(s2);
}

__device__ __forceinline__ void block_sum2(float& v1, float& v2, float* sred,
                                           int tid, int nwarp) {
    int lane = tid & 31, warp = tid >> 5;
#pragma unroll
    for (int o = 16; o; o >>= 1) {
        v1 += __shfl_xor_sync(0xffffffffu, v1, o);
        v2 += __shfl_xor_sync(0xffffffffu, v2, o);
    }
    if (!lane) { sred[warp] = v1; sred[32 + warp] = v2; }
    __syncthreads();
    if (!tid) {
        float a = 0.f, b = 0.f;
        for (int w = 0; w < nwarp; ++w) { a += sred[w]; b += sred[32 + w]; }
        v1 = a; v2 = b;
    }
}

// ============================================================
// Kernel 3: JS KL partial sums
// ============================================================
__global__ void js_kl_kernel(const float* __restrict__ sr,
                             const float* __restrict__ hr) {
    __shared__ float sred[64];
    int tid = threadIdx.x;
    int pos = blockIdx.x * blockDim.x + tid;
    float l1 = g_lse[pos], l2 = g_lse[DFEAT + pos];
    float acc1 = 0.f, acc2 = 0.f;
#pragma unroll 4
    for (int b = 0; b < BSZ; ++b) {
        float lx = sr[(long)b * DFEAT + pos] - l1;
        float ly = hr[(long)b * DFEAT + pos] - l2;
        float px = exp2f(lx * L2E);
        float py = exp2f(ly * L2E);
        float mm = 0.5f * (px + py);
        float lm = __logf(mm);
        acc1 += mm * (lm - lx);
        acc2 += mm * (lm - ly);
    }
    block_sum2(acc1, acc2, sred, tid, 8);
    if (!tid) {
        g_js[blockIdx.x]         = acc1;
        g_js[JSBLK + blockIdx.x] = acc2;
    }
}

// ============================================================
// Kernel 4: adversarial term: sum softplus(-x)
// ============================================================
__global__ void adv_kernel(const float* __restrict__ d) {
    __shared__ float sred[64];
    int tid = threadIdx.x;  // 256
    float s = 0.f, dummy = 0.f;
    for (int i = tid; i < ADVN; i += 256) {
        float x = d[i];
        s += fmaxf(-x, 0.f) + log1pf(__expf(-fabsf(x)));
    }
    block_sum2(s, dummy, sred, tid, 8);
    if (!tid) g_adv = s;
}

// ============================================================
// Kernel 5: persistent single-block entropic GW (the hot one)
// ============================================================
#define P68 68   // float4-friendly pitch for c1/c2/T/M1
#define P65 65   // conflict-free row+col pitch for Mk
#define GW_SMEM_FLOATS (4 * 64 * P68 + 64 * P65 + 4 * 64 + 80)
#define GW_SMEM_BYTES  (GW_SMEM_FLOATS * 4)

__global__ __launch_bounds__(1024, 1) void gw_kernel() {
    extern __shared__ float sm[];
    float* c1  = sm;
    float* c2  = c1 + 64 * P68;
    float* Tm  = c2 + 64 * P68;
    float* M1  = Tm + 64 * P68;
    float* Mk  = M1 + 64 * P68;
    float* sa  = Mk + 64 * P65;
    float* sb  = sa + 64;
    float* r1  = sb + 64;
    float* r2  = r1 + 64;
    float* red = r2 + 64;   // 80 floats

    int tid  = threadIdx.x;
    int lane = tid & 31, warp = tid >> 5;
    int ii = tid >> 4, jq = (tid & 15) << 2;   // element-parallel mapping

    // ---- 1) reduce gram partials into c1/c2 ----
    for (int m = 0; m < 2; ++m) {
        float* C = m ? c2 : c1;
        for (int e = tid; e < 4096; e += 1024) {
            const float* p = g_part + m * KCHUNK * 4096 + e;
            float s = 0.f;
#pragma unroll 8
            for (int c = 0; c < KCHUNK; ++c) s += p[c * 4096];
            C[(e >> 6) * P68 + (e & 63)] = s;
        }
    }
    __syncthreads();

    // ---- 2) distances + normalization ----
    if (tid < 64) r1[tid] = c1[tid * P68 + tid];
    else if (tid < 128) { int t = tid - 64; r2[t] = c2[t * P68 + t]; }
    __syncthreads();

    float lm1 = 0.f, lm2 = 0.f;
    for (int e = tid; e < 4096; e += 1024) {
        int i = e >> 6, j = e & 63;
        float d1 = sqrtf(fmaxf(r1[i] + r1[j] - 2.f * c1[i * P68 + j], 0.f));
        float d2 = sqrtf(fmaxf(r2[i] + r2[j] - 2.f * c2[i * P68 + j], 0.f));
        c1[i * P68 + j] = d1;
        c2[i * P68 + j] = d2;
        lm1 = fmaxf(lm1, d1);
        lm2 = fmaxf(lm2, d2);
    }
#pragma unroll
    for (int o = 16; o; o >>= 1) {
        lm1 = fmaxf(lm1, __shfl_xor_sync(0xffffffffu, lm1, o));
        lm2 = fmaxf(lm2, __shfl_xor_sync(0xffffffffu, lm2, o));
    }
    if (!lane) { red[warp] = lm1; red[32 + warp] = lm2; }
    __syncthreads();
    if (!tid) {
        float a = red[0], b = red[32];
        for (int w = 1; w < 32; ++w) { a = fmaxf(a, red[w]); b = fmaxf(b, red[32 + w]); }
        red[64] = 1.f / a;
        red[65] = 1.f / b;
    }
    __syncthreads();
    float inv1 = red[64], inv2 = red[65];
    for (int e = tid; e < 4096; e += 1024) {
        int i = e >> 6, j = e & 63;
        c1[i * P68 + j] *= inv1;
        c2[i * P68 + j] *= inv2;
        Tm[i * P68 + j] = 1.f / 4096.f;
    }
    __syncthreads();

    // rowmeans of squared costs (constC components)
    if (tid < 64) {
        float s = 0.f;
        for (int j = 0; j < 64; ++j) { float v = c1[tid * P68 + j]; s = fmaf(v, v, s); }
        r1[tid] = s * (1.f / 64.f);
    } else if (tid < 128) {
        int t = tid - 64;
        float s = 0.f;
        for (int j = 0; j < 64; ++j) { float v = c2[t * P68 + j]; s = fmaf(v, v, s); }
        r2[t] = s * (1.f / 64.f);
    }
    __syncthreads();

    // ---- 3) 30 outer mirror-descent iterations ----
    for (int outer = 0; outer < OUTER; ++outer) {
        // M1 = T @ c2
        {
            float a0 = 0.f, a1 = 0.f, a2 = 0.f, a3 = 0.f;
#pragma unroll 8
            for (int k = 0; k < 64; ++k) {
                float tv = Tm[ii * P68 + k];
                float4 bv = *(const float4*)(c2 + k * P68 + jq);
                a0 = fmaf(tv, bv.x, a0);
                a1 = fmaf(tv, bv.y, a1);
                a2 = fmaf(tv, bv.z, a2);
                a3 = fmaf(tv, bv.w, a3);
            }
            *(float4*)(M1 + ii * P68 + jq) = make_float4(a0, a1, a2, a3);
        }
        __syncthreads();
        // Mk = (2 * c1@M1 - constC) * (log2e/eps)   [base-2 log-kernel]
        {
            float p0 = 0.f, p1 = 0.f, p2 = 0.f, p3 = 0.f;
#pragma unroll 8
            for (int k = 0; k < 64; ++k) {
                float av = c1[ii * P68 + k];
                float4 mv = *(const float4*)(M1 + k * P68 + jq);
                p0 = fmaf(av, mv.x, p0);
                p1 = fmaf(av, mv.y, p1);
                p2 = fmaf(av, mv.z, p2);
                p3 = fmaf(av, mv.w, p3);
            }
            float ri = r1[ii];
            Mk[ii * P65 + jq + 0] = (2.f * p0 - ri - r2[jq + 0]) * KSCALE;
            Mk[ii * P65 + jq + 1] = (2.f * p1 - ri - r2[jq + 1]) * KSCALE;
            Mk[ii * P65 + jq + 2] = (2.f * p2 - ri - r2[jq + 2]) * KSCALE;
            Mk[ii * P65 + jq + 3] = (2.f * p3 - ri - r2[jq + 3]) * KSCALE;
        }
        if (tid < 64) sb[tid] = 0.f;
        __syncthreads();

        // ---- log-domain Sinkhorn, 200 iterations, base-2 ----
        for (int it = 0; it < INNER; ++it) {
            {   // a-update: rows (warp w handles rows w and w+32)
                int ra = warp, rb = warp + 32;
                float bb0 = sb[lane], bb1 = sb[lane + 32];
                float x0 = Mk[ra * P65 + lane] + bb0;
                float x1 = Mk[ra * P65 + lane + 32] + bb1;
                float y0 = Mk[rb * P65 + lane] + bb0;
                float y1 = Mk[rb * P65 + lane + 32] + bb1;
                float mx = fmaxf(x0, x1), my = fmaxf(y0, y1);
#pragma unroll
                for (int o = 16; o; o >>= 1) {
                    mx = fmaxf(mx, __shfl_xor_sync(0xffffffffu, mx, o));
                    my = fmaxf(my, __shfl_xor_sync(0xffffffffu, my, o));
                }
                float sx = exp2f(x0 - mx) + exp2f(x1 - mx);
                float sy = exp2f(y0 - my) + exp2f(y1 - my);
#pragma unroll
                for (int o = 16; o; o >>= 1) {
                    sx += __shfl_xor_sync(0xffffffffu, sx, o);
                    sy += __shfl_xor_sync(0xffffffffu, sy, o);
                }
                if (!lane) {
                    sa[ra] = LOGP2 - (mx + __log2f(sx));
                    sa[rb] = LOGP2 - (my + __log2f(sy));
                }
                __syncthreads();
            }
            {   // b-update: columns (pitch 65 => conflict-free)
                int ca = warp, cb = warp + 32;
                float aa0 = sa[lane], aa1 = sa[lane + 32];
                float x0 = Mk[lane * P65 + ca] + aa0;
                float x1 = Mk[(lane + 32) * P65 + ca] + aa1;
                float y0 = Mk[lane * P65 + cb] + aa0;
                float y1 = Mk[(lane + 32) * P65 + cb] + aa1;
                float mx = fmaxf(x0, x1), my = fmaxf(y0, y1);
#pragma unroll
                for (int o = 16; o; o >>= 1) {
                    mx = fmaxf(mx, __shfl_xor_sync(0xffffffffu, mx, o));
                    my = fmaxf(my, __shfl_xor_sync(0xffffffffu, my, o));
                }
                float sx = exp2f(x0 - mx) + exp2f(x1 - mx);
                float sy = exp2f(y0 - my) + exp2f(y1 - my);
#pragma unroll
                for (int o = 16; o; o >>= 1) {
                    sx += __shfl_xor_sync(0xffffffffu, sx, o);
                    sy += __shfl_xor_sync(0xffffffffu, sy, o);
                }
                if (!lane) {
                    sb[ca] = LOGP2 - (mx + __log2f(sx));
                    sb[cb] = LOGP2 - (my + __log2f(sy));
                }
                __syncthreads();
            }
        }

        // T = 2^(a + Mk + b)
        {
            float ai = sa[ii];
#pragma unroll
            for (int q = 0; q < 4; ++q)
                Tm[ii * P68 + jq + q] =
                    exp2f(ai + Mk[ii * P65 + jq + q] + sb[jq + q]);
        }
        __syncthreads();
    }

    // ---- 4) gw = sum(tens(T) * T) with final T ----
    {
        float a0 = 0.f, a1 = 0.f, a2 = 0.f, a3 = 0.f;
#pragma unroll 8
        for (int k = 0; k < 64; ++k) {
            float tv = Tm[ii * P68 + k];
            float4 bv = *(const float4*)(c2 + k * P68 + jq);
            a0 = fmaf(tv, bv.x, a0);
            a1 = fmaf(tv, bv.y, a1);
            a2 = fmaf(tv, bv.z, a2);
            a3 = fmaf(tv, bv.w, a3);
        }
        *(float4*)(M1 + ii * P68 + jq) = make_float4(a0, a1, a2, a3);
    }
    __syncthreads();
    {
        float p0 = 0.f, p1 = 0.f, p2 = 0.f, p3 = 0.f;
#pragma unroll 8
        for (int k = 0; k < 64; ++k) {
            float av = c1[ii * P68 + k];
            float4 mv = *(const float4*)(M1 + k * P68 + jq);
            p0 = fmaf(av, mv.x, p0);
            p1 = fmaf(av, mv.y, p1);
            p2 = fmaf(av, mv.z, p2);
            p3 = fmaf(av, mv.w, p3);
        }
        float ri = r1[ii];
        float local =
            (ri + r2[jq + 0] - 2.f * p0) * Tm[ii * P68 + jq + 0] +
            (ri + r2[jq + 1] - 2.f * p1) * Tm[ii * P68 + jq + 1] +
            (ri + r2[jq + 2] - 2.f * p2) * Tm[ii * P68 + jq + 2] +
            (ri + r2[jq + 3] - 2.f * p3) * Tm[ii * P68 + jq + 3];
#pragma unroll
        for (int o = 16; o; o >>= 1)
            local += __shfl_xor_sync(0xffffffffu, local, o);
        if (!lane) red[warp] = local;
        __syncthreads();
        if (!tid) {
            float s = 0.f;
            for (int w = 0; w < 32; ++w) s += red[w];
            g_gw = s;
        }
    }
}

// ============================================================
// Kernel 6: final softmax-weighted combine
// ============================================================
__global__ void final_kernel(float* __restrict__ out) {
    __shared__ float sred[64];
    int tid = threadIdx.x;  // 256
    float s1 = 0.f, s2 = 0.f;
    for (int i = tid; i < JSBLK; i += 256) {
        s1 += g_js[i];
        s2 += g_js[JSBLK + i];
    }
    block_sum2(s1, s2, sred, tid, 8);
    if (!tid) {
        float js  = 0.5f * (s1 + s2) * (1.f / 64.f);
        float adv = g_adv * (1.f / (float)ADVN);
        float gw  = g_gw;
        float mx = fmaxf(gw, fmaxf(js, adv));
        float w0 = expf((gw - mx) * 10.f);
        float w1 = expf((js - mx) * 10.f);
        float w2 = expf((adv - mx) * 10.f);
        float den = w0 + w1 + w2;
        out[0] = (gw * w0 + js * w1 + adv * w2) / den;
    }
}

// ============================================================
extern "C" void kernel_launch(void* const* d_in, const int* in_sizes, int n_in,
                              void* d_out, int out_size) {
    // lr, sr, hr are the three big tensors (in metadata order);
    // disc_fake is the single 16384-element tensor wherever it sits.
    const float* big[3] = {nullptr, nullptr, nullptr};
    const float* df = nullptr;
    int nb = 0;
    for (int i = 0; i < n_in; ++i) {
        if (in_sizes[i] == ADVN) df = (const float*)d_in[i];
        else if (nb < 3) big[nb++] = (const float*)d_in[i];
    }
    const float* lr = big[0];
    const float* sr = big[1];
    const float* hr = big[2];
    float* out = (float*)d_out;
    (void)out_size;

    cudaFuncSetAttribute(gw_kernel, cudaFuncAttributeMaxDynamicSharedMemorySize,
                         GW_SMEM_BYTES);

    gram_kernel<<<dim3(KCHUNK, 2), 256>>>(lr, sr);
    js_lse_kernel<<<JSBLK, 256>>>(sr, hr);
    js_kl_kernel<<<JSBLK, 256>>>(sr, hr);
    adv_kernel<<<1, 256>>>(df);
    gw_kernel<<<1, 1024, GW_SMEM_BYTES>>>();
    final_kernel<<<1, 256>>>(out);
}

// round 2
// speedup vs baseline: 1.8090x; 1.8090x over previous
#include <cuda_runtime.h>
#include <math.h>

#define BSZ      64
#define DFEAT    196608            // 3*256*256
#define KCHUNK   128               // gram partial blocks per matrix
#define CHUNK    (DFEAT / KCHUNK)  // 1536
#define TK       128
#define NTILE    (CHUNK / TK)      // 12
#define JSBLK    768
#define ADVN     16384
#define OUTER    30
#define INNER    200
#define L2E      1.4426950408889634f
#define EPS_GW   0.0005f
#define KSCALE   (L2E / EPS_GW)    // base-2 scaling of -cost/eps
#define LOGP2    (-6.0f)           // log2(1/64)

// ---- device scratch ----
__device__ float g_part[2 * KCHUNK * 4096];  // gram partials, 4 MB
__device__ float g_c[2 * 4096];              // reduced grams
__device__ float g_lse[2 * DFEAT];           // per-position LSE for sr/hr
__device__ float g_js[2 * JSBLK];            // per-block KL partial sums
__device__ float g_adv;
__device__ float g_gw;

__device__ __forceinline__ float fex2(float x) {
    float r;
    asm("ex2.approx.ftz.f32 %0, %1;" : "=f"(r) : "f"(x));
    return r;
}
__device__ __forceinline__ float flg2(float x) {
    float r;
    asm("lg2.approx.f32 %0, %1;" : "=f"(r) : "f"(x));
    return r;
}

// ============================================================
// Kernel 1: Gram partials  G = X X^T  (64x64), K-chunked
// k-major shared tile -> float4 LDS in the FMA loop
// ============================================================
__global__ __launch_bounds__(256) void gram_kernel(const float* __restrict__ lr,
                                                   const float* __restrict__ sr) {
    __shared__ float tile2[TK][68];   // [k][row], rows padded to 68
    const float* X = blockIdx.y ? sr : lr;
    float* out = g_part + (blockIdx.y * KCHUNK + blockIdx.x) * 4096;

    int tid = threadIdx.x;            // 256 threads
    int ty = tid >> 4, tx = tid & 15;
    float acc[4][4];
#pragma unroll
    for (int r = 0; r < 4; ++r)
#pragma unroll
        for (int c = 0; c < 4; ++c) acc[r][c] = 0.f;

    long k0base = (long)blockIdx.x * CHUNK;
    for (int t = 0; t < NTILE; ++t) {
        long k0 = k0base + (long)t * TK;
        for (int idx = tid; idx < 64 * TK; idx += 256) {
            int r = idx >> 7;         // TK = 128
            int c = idx & 127;
            tile2[c][r] = X[(long)r * DFEAT + k0 + c];
        }
        __syncthreads();
#pragma unroll 4
        for (int k = 0; k < TK; ++k) {
            float4 av = *(const float4*)&tile2[k][4 * ty];
            float4 bv = *(const float4*)&tile2[k][4 * tx];
            acc[0][0] = fmaf(av.x, bv.x, acc[0][0]);
            acc[0][1] = fmaf(av.x, bv.y, acc[0][1]);
            acc[0][2] = fmaf(av.x, bv.z, acc[0][2]);
            acc[0][3] = fmaf(av.x, bv.w, acc[0][3]);
            acc[1][0] = fmaf(av.y, bv.x, acc[1][0]);
            acc[1][1] = fmaf(av.y, bv.y, acc[1][1]);
            acc[1][2] = fmaf(av.y, bv.z, acc[1][2]);
            acc[1][3] = fmaf(av.y, bv.w, acc[1][3]);
            acc[2][0] = fmaf(av.z, bv.x, acc[2][0]);
            acc[2][1] = fmaf(av.z, bv.y, acc[2][1]);
            acc[2][2] = fmaf(av.z, bv.z, acc[2][2]);
            acc[2][3] = fmaf(av.z, bv.w, acc[2][3]);
            acc[3][0] = fmaf(av.w, bv.x, acc[3][0]);
            acc[3][1] = fmaf(av.w, bv.y, acc[3][1]);
            acc[3][2] = fmaf(av.w, bv.z, acc[3][2]);
            acc[3][3] = fmaf(av.w, bv.w, acc[3][3]);
        }
        __syncthreads();
    }
#pragma unroll
    for (int r = 0; r < 4; ++r)
#pragma unroll
        for (int c = 0; c < 4; ++c)
            out[(4 * ty + r) * 64 + 4 * tx + c] = acc[r][c];
}

// ============================================================
// Kernel 1b: reduce gram partials (multi-block, fast)
// ============================================================
__global__ void gram_reduce_kernel() {
    int o = blockIdx.x * blockDim.x + threadIdx.x;  // 8192
    const float* p = g_part + (o >> 12) * (KCHUNK * 4096) + (o & 4095);
    float s = 0.f;
#pragma unroll 8
    for (int c = 0; c < KCHUNK; ++c) s += p[c * 4096];
    g_c[o] = s;
}

// ============================================================
// Kernel 2: per-position online logsumexp over batch (sr, hr)
// ============================================================
__global__ void js_lse_kernel(const float* __restrict__ sr,
                              const float* __restrict__ hr) {
    int pos = blockIdx.x * blockDim.x + threadIdx.x;
    const float* ps = sr + pos;
    const float* ph = hr + pos;
    float m1 = -1e30f, s1 = 0.f, m2 = -1e30f, s2 = 0.f;
#pragma unroll 4
    for (int b = 0; b < BSZ; ++b) {
        float v = ps[(long)b * DFEAT];
        float nm = fmaxf(m1, v);
        s1 = s1 * exp2f((m1 - nm) * L2E) + exp2f((v - nm) * L2E);
        m1 = nm;
        float w = ph[(long)b * DFEAT];
        float nw = fmaxf(m2, w);
        s2 = s2 * exp2f((m2 - nw) * L2E) + exp2f((w - nw) * L2E);
        m2 = nw;
    }
    g_lse[pos]         = m1 + __logf(s1);
    g_lse[DFEAT + pos] = m2 + __logf(s2);
}

__device__ __forceinline__ void block_sum2(float& v1, float& v2, float* sred,
                                           int tid, int nwarp) {
    int lane = tid & 31, warp = tid >> 5;
#pragma unroll
    for (int o = 16; o; o >>= 1) {
        v1 += __shfl_xor_sync(0xffffffffu, v1, o);
        v2 += __shfl_xor_sync(0xffffffffu, v2, o);
    }
    if (!lane) { sred[warp] = v1; sred[32 + warp] = v2; }
    __syncthreads();
    if (!tid) {
        float a = 0.f, b = 0.f;
        for (int w = 0; w < nwarp; ++w) { a += sred[w]; b += sred[32 + w]; }
        v1 = a; v2 = b;
    }
}

// ============================================================
// Kernel 3: JS KL partial sums
// ============================================================
__global__ void js_kl_kernel(const float* __restrict__ sr,
                             const float* __restrict__ hr) {
    __shared__ float sred[64];
    int tid = threadIdx.x;
    int pos = blockIdx.x * blockDim.x + tid;
    float l1 = g_lse[pos], l2 = g_lse[DFEAT + pos];
    float acc1 = 0.f, acc2 = 0.f;
#pragma unroll 4
    for (int b = 0; b < BSZ; ++b) {
        float lx = sr[(long)b * DFEAT + pos] - l1;
        float ly = hr[(long)b * DFEAT + pos] - l2;
        float px = exp2f(lx * L2E);
        float py = exp2f(ly * L2E);
        float mm = 0.5f * (px + py);
        float lm = __logf(mm);
        acc1 += mm * (lm - lx);
        acc2 += mm * (lm - ly);
    }
    block_sum2(acc1, acc2, sred, tid, 8);
    if (!tid) {
        g_js[blockIdx.x]         = acc1;
        g_js[JSBLK + blockIdx.x] = acc2;
    }
}

// ============================================================
// Kernel 4: adversarial term
// ============================================================
__global__ void adv_kernel(const float* __restrict__ d) {
    __shared__ float sred[64];
    int tid = threadIdx.x;
    float s = 0.f, dummy = 0.f;
    for (int i = tid; i < ADVN; i += 256) {
        float x = d[i];
        s += fmaxf(-x, 0.f) + log1pf(__expf(-fabsf(x)));
    }
    block_sum2(s, dummy, sred, tid, 8);
    if (!tid) g_adv = s;
}

// ============================================================
// Kernel 5: persistent single-block entropic GW
// ============================================================
#define P68 68
#define GW_SMEM_FLOATS (6 * 64 * P68 + 4 * 64 + 80)
#define GW_SMEM_BYTES  (GW_SMEM_FLOATS * 4)

__global__ __launch_bounds__(1024, 1) void gw_kernel() {
    extern __shared__ float sm[];
    float* c1  = sm;                 // 64*68
    float* c2  = c1 + 64 * P68;
    float* Tm  = c2 + 64 * P68;
    float* M1  = Tm + 64 * P68;
    float* Mk  = M1 + 64 * P68;      // row-major, float4 access
    float* Mt  = Mk + 64 * P68;      // transposed copy
    float* sa  = Mt + 64 * P68;
    float* sb  = sa + 64;
    float* r1  = sb + 64;
    float* r2  = r1 + 64;
    float* red = r2 + 64;            // 80 floats

    int tid  = threadIdx.x;
    int lane = tid & 31, warp = tid >> 5;
    int ii = tid >> 4, jq = (tid & 15) << 2;   // matmul mapping
    int rr = tid >> 4, tt = tid & 15;          // sinkhorn mapping (16 lanes/row)

    // ---- 1) load reduced grams ----
    for (int e = tid; e < 4096; e += 1024) {
        c1[(e >> 6) * P68 + (e & 63)] = g_c[e];
        c2[(e >> 6) * P68 + (e & 63)] = g_c[4096 + e];
    }
    __syncthreads();

    // ---- 2) distances + normalization ----
    if (tid < 64) r1[tid] = c1[tid * P68 + tid];
    else if (tid < 128) { int t = tid - 64; r2[t] = c2[t * P68 + t]; }
    __syncthreads();

    float lm1 = 0.f, lm2 = 0.f;
    for (int e = tid; e < 4096; e += 1024) {
        int i = e >> 6, j = e & 63;
        float d1 = sqrtf(fmaxf(r1[i] + r1[j] - 2.f * c1[i * P68 + j], 0.f));
        float d2 = sqrtf(fmaxf(r2[i] + r2[j] - 2.f * c2[i * P68 + j], 0.f));
        c1[i * P68 + j] = d1;
        c2[i * P68 + j] = d2;
        lm1 = fmaxf(lm1, d1);
        lm2 = fmaxf(lm2, d2);
    }
#pragma unroll
    for (int o = 16; o; o >>= 1) {
        lm1 = fmaxf(lm1, __shfl_xor_sync(0xffffffffu, lm1, o));
        lm2 = fmaxf(lm2, __shfl_xor_sync(0xffffffffu, lm2, o));
    }
    if (!lane) { red[warp] = lm1; red[32 + warp] = lm2; }
    __syncthreads();
    if (!tid) {
        float a = red[0], b = red[32];
        for (int w = 1; w < 32; ++w) { a = fmaxf(a, red[w]); b = fmaxf(b, red[32 + w]); }
        red[64] = 1.f / a;
        red[65] = 1.f / b;
    }
    __syncthreads();
    float inv1 = red[64], inv2 = red[65];
    for (int e = tid; e < 4096; e += 1024) {
        int i = e >> 6, j = e & 63;
        c1[i * P68 + j] *= inv1;
        c2[i * P68 + j] *= inv2;
        Tm[i * P68 + j] = 1.f / 4096.f;
    }
    __syncthreads();

    // rowmeans of squared costs
    if (tid < 64) {
        float s = 0.f;
        for (int j = 0; j < 64; ++j) { float v = c1[tid * P68 + j]; s = fmaf(v, v, s); }
        r1[tid] = s * (1.f / 64.f);
    } else if (tid < 128) {
        int t = tid - 64;
        float s = 0.f;
        for (int j = 0; j < 64; ++j) { float v = c2[t * P68 + j]; s = fmaf(v, v, s); }
        r2[t] = s * (1.f / 64.f);
    }
    __syncthreads();

    // ---- 3) outer mirror-descent ----
    for (int outer = 0; outer < OUTER; ++outer) {
        // M1 = T @ c2
        {
            float a0 = 0.f, a1 = 0.f, a2 = 0.f, a3 = 0.f;
#pragma unroll 8
            for (int k = 0; k < 64; ++k) {
                float tv = Tm[ii * P68 + k];
                float4 bv = *(const float4*)(c2 + k * P68 + jq);
                a0 = fmaf(tv, bv.x, a0);
                a1 = fmaf(tv, bv.y, a1);
                a2 = fmaf(tv, bv.z, a2);
                a3 = fmaf(tv, bv.w, a3);
            }
            *(float4*)(M1 + ii * P68 + jq) = make_float4(a0, a1, a2, a3);
        }
        __syncthreads();
        // Mk = (2 c1@M1 - constC) * KSCALE ; write row-major + transposed
        {
            float p0 = 0.f, p1 = 0.f, p2 = 0.f, p3 = 0.f;
#pragma unroll 8
            for (int k = 0; k < 64; ++k) {
                float av = c1[ii * P68 + k];
                float4 mv = *(const float4*)(M1 + k * P68 + jq);
                p0 = fmaf(av, mv.x, p0);
                p1 = fmaf(av, mv.y, p1);
                p2 = fmaf(av, mv.z, p2);
                p3 = fmaf(av, mv.w, p3);
            }
            float ri = r1[ii];
            float v0 = (2.f * p0 - ri - r2[jq + 0]) * KSCALE;
            float v1 = (2.f * p1 - ri - r2[jq + 1]) * KSCALE;
            float v2 = (2.f * p2 - ri - r2[jq + 2]) * KSCALE;
            float v3 = (2.f * p3 - ri - r2[jq + 3]) * KSCALE;
            *(float4*)(Mk + ii * P68 + jq) = make_float4(v0, v1, v2, v3);
            Mt[(jq + 0) * P68 + ii] = v0;
            Mt[(jq + 1) * P68 + ii] = v1;
            Mt[(jq + 2) * P68 + ii] = v2;
            Mt[(jq + 3) * P68 + ii] = v3;
        }
        if (tid < 64) sb[tid] = 0.f;
        __syncthreads();

        // ---- Sinkhorn: a1 (max-based), then 199 x {b,a}, then final b ----
        // a-update #1: b = 0, z = Mk unbounded -> need max
        {
            float4 mk = *(const float4*)(Mk + rr * P68 + 4 * tt);
            float m = fmaxf(fmaxf(mk.x, mk.y), fmaxf(mk.z, mk.w));
#pragma unroll
            for (int o = 8; o; o >>= 1)
                m = fmaxf(m, __shfl_xor_sync(0xffffffffu, m, o));
            float s = fex2(mk.x - m) + fex2(mk.y - m) +
                      fex2(mk.z - m) + fex2(mk.w - m);
#pragma unroll
            for (int o = 8; o; o >>= 1)
                s += __shfl_xor_sync(0xffffffffu, s, o);
            if (!tt) sa[rr] = LOGP2 - (m + flg2(s));
        }
        __syncthreads();

        // After the first a-update, all z = Mk + a + b <= -6: no max needed.
#pragma unroll 1
        for (int it = 0; it < INNER - 1; ++it) {
            {   // b-phase: rr = column
                float4 mt = *(const float4*)(Mt + rr * P68 + 4 * tt);
                float4 av = *(const float4*)(sa + 4 * tt);
                float bo = sb[rr];
                float s = fex2(mt.x + av.x + bo) + fex2(mt.y + av.y + bo) +
                          fex2(mt.z + av.z + bo) + fex2(mt.w + av.w + bo);
#pragma unroll
                for (int o = 8; o; o >>= 1)
                    s += __shfl_xor_sync(0xffffffffu, s, o);
                if (!tt) sb[rr] = bo + (LOGP2 - flg2(s));
                __syncthreads();
            }
            {   // a-phase: rr = row
                float4 mk = *(const float4*)(Mk + rr * P68 + 4 * tt);
                float4 bv = *(const float4*)(sb + 4 * tt);
                float ao = sa[rr];
                float s = fex2(mk.x + bv.x + ao) + fex2(mk.y + bv.y + ao) +
                          fex2(mk.z + bv.z + ao) + fex2(mk.w + bv.w + ao);
#pragma unroll
                for (int o = 8; o; o >>= 1)
                    s += __shfl_xor_sync(0xffffffffu, s, o);
                if (!tt) sa[rr] = ao + (LOGP2 - flg2(s));
                __syncthreads();
            }
        }
        {   // final b-phase (b200)
            float4 mt = *(const float4*)(Mt + rr * P68 + 4 * tt);
            float4 av = *(const float4*)(sa + 4 * tt);
            float bo = sb[rr];
            float s = fex2(mt.x + av.x + bo) + fex2(mt.y + av.y + bo) +
                      fex2(mt.z + av.z + bo) + fex2(mt.w + av.w + bo);
#pragma unroll
            for (int o = 8; o; o >>= 1)
                s += __shfl_xor_sync(0xffffffffu, s, o);
            if (!tt) sb[rr] = bo + (LOGP2 - flg2(s));
            __syncthreads();
        }

        // T = 2^(a + Mk + b)
        {
            float ai = sa[ii];
            float4 mk = *(const float4*)(Mk + ii * P68 + jq);
            float4 bv = *(const float4*)(sb + jq);
            Tm[ii * P68 + jq + 0] = fex2(ai + mk.x + bv.x);
            Tm[ii * P68 + jq + 1] = fex2(ai + mk.y + bv.y);
            Tm[ii * P68 + jq + 2] = fex2(ai + mk.z + bv.z);
            Tm[ii * P68 + jq + 3] = fex2(ai + mk.w + bv.w);
        }
        __syncthreads();
    }

    // ---- 4) gw = sum(tens(T) * T) ----
    {
        float a0 = 0.f, a1 = 0.f, a2 = 0.f, a3 = 0.f;
#pragma unroll 8
        for (int k = 0; k < 64; ++k) {
            float tv = Tm[ii * P68 + k];
            float4 bv = *(const float4*)(c2 + k * P68 + jq);
            a0 = fmaf(tv, bv.x, a0);
            a1 = fmaf(tv, bv.y, a1);
            a2 = fmaf(tv, bv.z, a2);
            a3 = fmaf(tv, bv.w, a3);
        }
        *(float4*)(M1 + ii * P68 + jq) = make_float4(a0, a1, a2, a3);
    }
    __syncthreads();
    {
        float p0 = 0.f, p1 = 0.f, p2 = 0.f, p3 = 0.f;
#pragma unroll 8
        for (int k = 0; k < 64; ++k) {
            float av = c1[ii * P68 + k];
            float4 mv = *(const float4*)(M1 + k * P68 + jq);
            p0 = fmaf(av, mv.x, p0);
            p1 = fmaf(av, mv.y, p1);
            p2 = fmaf(av, mv.z, p2);
            p3 = fmaf(av, mv.w, p3);
        }
        float ri = r1[ii];
        float local =
            (ri + r2[jq + 0] - 2.f * p0) * Tm[ii * P68 + jq + 0] +
            (ri + r2[jq + 1] - 2.f * p1) * Tm[ii * P68 + jq + 1] +
            (ri + r2[jq + 2] - 2.f * p2) * Tm[ii * P68 + jq + 2] +
            (ri + r2[jq + 3] - 2.f * p3) * Tm[ii * P68 + jq + 3];
#pragma unroll
        for (int o = 16; o; o >>= 1)
            local += __shfl_xor_sync(0xffffffffu, local, o);
        if (!lane) red[warp] = local;
        __syncthreads();
        if (!tid) {
            float s = 0.f;
            for (int w = 0; w < 32; ++w) s += red[w];
            g_gw = s;
        }
    }
}

// ============================================================
// Kernel 6: final combine
// ============================================================
__global__ void final_kernel(float* __restrict__ out) {
    __shared__ float sred[64];
    int tid = threadIdx.x;
    float s1 = 0.f, s2 = 0.f;
    for (int i = tid; i < JSBLK; i += 256) {
        s1 += g_js[i];
        s2 += g_js[JSBLK + i];
    }
    block_sum2(s1, s2, sred, tid, 8);
    if (!tid) {
        float js  = 0.5f * (s1 + s2) * (1.f / 64.f);
        float adv = g_adv * (1.f / (float)ADVN);
        float gw  = g_gw;
        float mx = fmaxf(gw, fmaxf(js, adv));
        float w0 = expf((gw - mx) * 10.f);
        float w1 = expf((js - mx) * 10.f);
        float w2 = expf((adv - mx) * 10.f);
        float den = w0 + w1 + w2;
        out[0] = (gw * w0 + js * w1 + adv * w2) / den;
    }
}

// ============================================================
extern "C" void kernel_launch(void* const* d_in, const int* in_sizes, int n_in,
                              void* d_out, int out_size) {
    const float* big[3] = {nullptr, nullptr, nullptr};
    const float* df = nullptr;
    int nb = 0;
    for (int i = 0; i < n_in; ++i) {
        if (in_sizes[i] == ADVN) df = (const float*)d_in[i];
        else if (nb < 3) big[nb++] = (const float*)d_in[i];
    }
    const float* lr = big[0];
    const float* sr = big[1];
    const float* hr = big[2];
    float* out = (float*)d_out;
    (void)out_size;

    cudaFuncSetAttribute(gw_kernel, cudaFuncAttributeMaxDynamicSharedMemorySize,
                         GW_SMEM_BYTES);

    gram_kernel<<<dim3(KCHUNK, 2), 256>>>(lr, sr);
    gram_reduce_kernel<<<32, 256>>>();
    js_lse_kernel<<<JSBLK, 256>>>(sr, hr);
    js_kl_kernel<<<JSBLK, 256>>>(sr, hr);
    adv_kernel<<<1, 256>>>(df);
    gw_kernel<<<1, 1024, GW_SMEM_BYTES>>>();
    final_kernel<<<1, 256>>>(out);
}